// round 12
// baseline (speedup 1.0000x reference)
#include <cuda_runtime.h>

// Problem constants
#define NB   32      // batch
#define NIN  2048    // input capsules
#define ROW  1024    // NOUT*DD floats per (b,i) row
// Weighted passes (row-per-warp):
#define SLICES 8     // blocks per batch item (grid 256 = single resident wave)
#define WPBLK  8     // warps per block
#define IPW  32      // input rows per warp
// Pass 0 (column-per-thread, high occupancy):
#define SLICES0 32   // blocks per batch item (grid 1024, ~6 blocks/SM)
#define RPB0 (NIN / SLICES0)   // 64 rows per block

// Scratch (static device memory; no runtime allocation)
__device__ float g_partials[NB * SLICES0 * ROW];  // 4 MB (max of both pass shapes)
__device__ float g_ow[NB * ROW];                  // out0 (round1) / out0+out1 (round2)
__device__ int   g_cnt[NB];                       // zero-init; self-resetting

// ---------------------------------------------------------------------------
// Shared last-block epilogue: reduce NSL partials for batch b in fixed order,
// add bias, squash, update g_ow / write output, reset counter (replay-safe).
// ---------------------------------------------------------------------------
template<int NSL, int OW_MODE, int FINAL_OUT>
__device__ __forceinline__ void last_block_epilogue(
    int b, const float* __restrict__ bias, float* __restrict__ dout)
{
    const int t = threadIdx.x;
    const float4* pp = reinterpret_cast<const float4*>(g_partials) + (size_t)b * NSL * 256;
    float4 r = make_float4(0.f, 0.f, 0.f, 0.f);
#pragma unroll 8
    for (int s2 = 0; s2 < NSL; s2++) {
        float4 v = __ldcg(pp + s2 * 256 + t);   // L2 (other SMs wrote these)
        r.x += v.x; r.y += v.y; r.z += v.z; r.w += v.w;
    }
    float4 bb = reinterpret_cast<const float4*>(bias)[t];
    r.x += bb.x; r.y += bb.y; r.z += bb.z; r.w += bb.w;

    // squash over d=16 (4 threads per capsule j)
    float n2 = r.x * r.x + r.y * r.y + r.z * r.z + r.w * r.w;
    n2 += __shfl_xor_sync(0xffffffffu, n2, 1);
    n2 += __shfl_xor_sync(0xffffffffu, n2, 2);
    float scale = n2 / ((1.0f + n2) * sqrtf(n2 + 1e-7f));
    float4 o = make_float4(r.x * scale, r.y * scale, r.z * scale, r.w * scale);

    if (FINAL_OUT)
        reinterpret_cast<float4*>(dout)[b * 256 + t] = o;
    if (OW_MODE == 1) {
        reinterpret_cast<float4*>(g_ow)[b * 256 + t] = o;
    } else if (OW_MODE == 2) {
        float4 c = reinterpret_cast<const float4*>(g_ow)[b * 256 + t];
        c.x += o.x; c.y += o.y; c.z += o.z; c.w += o.w;
        reinterpret_cast<float4*>(g_ow)[b * 256 + t] = c;
    }

    if (t == 0) g_cnt[b] = 0;   // reset for next round / next graph replay
}

// ---------------------------------------------------------------------------
// Publish-then-arrive: ALL threads store partials, fence, BARRIER, then t0
// arrives on the batch counter. The barrier guarantees every thread's store
// is issued (and fenced) before this block is counted.
// Returns true iff this block is the last arriver for batch b.
// ---------------------------------------------------------------------------
template<int NSL>
__device__ __forceinline__ bool arrive_last(int b)
{
    __threadfence();     // publish this thread's partial store
    __syncthreads();     // ALL threads have stored+fenced before t0 arrives
    __shared__ int isLast;
    if (threadIdx.x == 0) {
        int old = atomicAdd(&g_cnt[b], 1);
        isLast = (old == NSL - 1);
    }
    __syncthreads();
    return isLast != 0;
}

// ---------------------------------------------------------------------------
// Pass 0 (uniform 1/64): column-per-thread. Thread t sums float4-column t of
// x[b, rows, :] over RPB0 rows. No smem in the hot loop, no in-block reduce:
// each thread's partial is complete. Low regs -> ~6 blocks/SM -> 48 warps/SM.
// ---------------------------------------------------------------------------
__global__ void __launch_bounds__(256, 6)
route_pass0(const float* __restrict__ x, const float* __restrict__ bias,
            float* __restrict__ dout)
{
    const int b     = blockIdx.x >> 5;       // 32 slices per batch
    const int slice = blockIdx.x & 31;
    const int t     = threadIdx.x;

    const float4* base = reinterpret_cast<const float4*>(x)
        + ((size_t)b * NIN + (size_t)slice * RPB0) * 256;

    float4 acc = make_float4(0.f, 0.f, 0.f, 0.f);
    for (int ii = 0; ii < RPB0; ii += 8) {
        float4 v[8];
#pragma unroll
        for (int k = 0; k < 8; k++) v[k] = base[(size_t)(ii + k) * 256 + t];
#pragma unroll
        for (int k = 0; k < 8; k++) {
            acc.x += v[k].x; acc.y += v[k].y; acc.z += v[k].z; acc.w += v[k].w;
        }
    }
    acc.x *= 0.015625f; acc.y *= 0.015625f;   // 1/64 exact
    acc.z *= 0.015625f; acc.w *= 0.015625f;

    reinterpret_cast<float4*>(g_partials)[((size_t)b * SLICES0 + slice) * 256 + t] = acc;

    if (!arrive_last<SLICES0>(b)) return;
    last_block_epilogue<SLICES0, 1, 0>(b, bias, dout);
}

// ---------------------------------------------------------------------------
// Weighted pass (rounds 1 & 2): row-per-warp, w in shared, x2 row unroll.
// p_j = dot(x[j,:], ow[j,:]); a = softmax_j(p); acc += a_j * x[j,:].
// REVERSE: zigzag traversal for cross-pass L2 reuse.
// Lane mapping: float4 f = lane + 32*k -> j = (lane>>2) + 8k, d = (lane&3)*4.
// ---------------------------------------------------------------------------
template<int OW_MODE, int FINAL_OUT, int REVERSE>
__global__ void __launch_bounds__(256, 2)
route_passW(const float* __restrict__ x, const float* __restrict__ bias,
            float* __restrict__ dout)
{
    const int b     = blockIdx.x >> 3;
    const int slice = blockIdx.x & 7;
    const int wloc  = threadIdx.x >> 5;
    const int wb    = (slice << 3) | wloc;
    const int lane  = threadIdx.x & 31;

    __shared__ float4 wsh[256];            // routing weight vector for this b (4 KB)
    __shared__ float4 sbuf[WPBLK * 256];   // 32 KB (tail reduce)

    {
        const float4* owp = reinterpret_cast<const float4*>(g_ow) + (size_t)b * 256;
        wsh[threadIdx.x] = owp[threadIdx.x];
    }
    __syncthreads();

    float4 acc[8];
#pragma unroll
    for (int k = 0; k < 8; k++) acc[k] = make_float4(0.f, 0.f, 0.f, 0.f);

    const float4* base = reinterpret_cast<const float4*>(x)
        + ((size_t)b * NIN + (size_t)wb * IPW) * 256;

    for (int it = 0; it < IPW; it += 2) {
        const int ii0 = REVERSE ? (IPW - 1 - it) : it;
        const int ii1 = REVERSE ? (IPW - 2 - it) : (it + 1);
        const float4* r0 = base + (size_t)ii0 * 256;
        const float4* r1 = base + (size_t)ii1 * 256;

        float4 xv0[8], xv1[8];
#pragma unroll
        for (int k = 0; k < 8; k++) xv0[k] = r0[lane + 32 * k];
#pragma unroll
        for (int k = 0; k < 8; k++) xv1[k] = r1[lane + 32 * k];

        float p0[8], p1[8];
#pragma unroll
        for (int k = 0; k < 8; k++) {
            float4 w = wsh[lane + 32 * k];
            float t0 = xv0[k].x * w.x + xv0[k].y * w.y + xv0[k].z * w.z + xv0[k].w * w.w;
            float t1 = xv1[k].x * w.x + xv1[k].y * w.y + xv1[k].z * w.z + xv1[k].w * w.w;
            t0 += __shfl_xor_sync(0xffffffffu, t0, 1);
            t1 += __shfl_xor_sync(0xffffffffu, t1, 1);
            t0 += __shfl_xor_sync(0xffffffffu, t0, 2);
            t1 += __shfl_xor_sync(0xffffffffu, t1, 2);
            p0[k] = t0;   // dot over d=16, replicated within 4-lane group
            p1[k] = t1;
        }
        // softmax over all 64 j (two independent rows interleaved)
        float m0 = p0[0], m1 = p1[0];
#pragma unroll
        for (int k = 1; k < 8; k++) { m0 = fmaxf(m0, p0[k]); m1 = fmaxf(m1, p1[k]); }
        m0 = fmaxf(m0, __shfl_xor_sync(0xffffffffu, m0, 4));
        m1 = fmaxf(m1, __shfl_xor_sync(0xffffffffu, m1, 4));
        m0 = fmaxf(m0, __shfl_xor_sync(0xffffffffu, m0, 8));
        m1 = fmaxf(m1, __shfl_xor_sync(0xffffffffu, m1, 8));
        m0 = fmaxf(m0, __shfl_xor_sync(0xffffffffu, m0, 16));
        m1 = fmaxf(m1, __shfl_xor_sync(0xffffffffu, m1, 16));
        float a0[8], a1[8], s0 = 0.f, s1 = 0.f;
#pragma unroll
        for (int k = 0; k < 8; k++) {
            a0[k] = __expf(p0[k] - m0); s0 += a0[k];
            a1[k] = __expf(p1[k] - m1); s1 += a1[k];
        }
        s0 += __shfl_xor_sync(0xffffffffu, s0, 4);
        s1 += __shfl_xor_sync(0xffffffffu, s1, 4);
        s0 += __shfl_xor_sync(0xffffffffu, s0, 8);
        s1 += __shfl_xor_sync(0xffffffffu, s1, 8);
        s0 += __shfl_xor_sync(0xffffffffu, s0, 16);
        s1 += __shfl_xor_sync(0xffffffffu, s1, 16);
        float inv0 = 1.0f / s0, inv1 = 1.0f / s1;
#pragma unroll
        for (int k = 0; k < 8; k++) {
            float ak0 = a0[k] * inv0;
            float ak1 = a1[k] * inv1;
            acc[k].x = fmaf(ak1, xv1[k].x, fmaf(ak0, xv0[k].x, acc[k].x));
            acc[k].y = fmaf(ak1, xv1[k].y, fmaf(ak0, xv0[k].y, acc[k].y));
            acc[k].z = fmaf(ak1, xv1[k].z, fmaf(ak0, xv0[k].z, acc[k].z));
            acc[k].w = fmaf(ak1, xv1[k].w, fmaf(ak0, xv0[k].w, acc[k].w));
        }
    }

    // in-block reduce: 8 warp-accumulators -> 1 per-block partial
#pragma unroll
    for (int k = 0; k < 8; k++) sbuf[wloc * 256 + lane + 32 * k] = acc[k];
    __syncthreads();

    const int t = threadIdx.x;
    float4 s = make_float4(0.f, 0.f, 0.f, 0.f);
#pragma unroll
    for (int w2 = 0; w2 < WPBLK; w2++) {
        float4 v = sbuf[w2 * 256 + t];
        s.x += v.x; s.y += v.y; s.z += v.z; s.w += v.w;
    }
    reinterpret_cast<float4*>(g_partials)[((size_t)b * SLICES + slice) * 256 + t] = s;

    if (!arrive_last<SLICES>(b)) return;
    last_block_epilogue<SLICES, OW_MODE, FINAL_OUT>(b, bias, dout);
}

extern "C" void kernel_launch(void* const* d_in, const int* in_sizes, int n_in,
                              void* d_out, int out_size)
{
    const float* x    = (const float*)d_in[0];   // [32, 2048, 64, 16]
    const float* bias = (const float*)d_in[1];   // [64, 16]
    float* out = (float*)d_out;                  // [32, 64, 16]

    (void)in_sizes; (void)n_in; (void)out_size;

    dim3 g0(NB * SLICES0), gW(NB * SLICES), blk(256);

    // Round 0 (forward, column-mapped, high occupancy): uniform 1/64; g_ow = out0
    route_pass0<<<g0, blk>>>(x, bias, out);
    // Round 1 (REVERSE): softmax(dot(x, out0)); g_ow = out0 + out1
    route_passW<2, 0, 1><<<gW, blk>>>(x, bias, out);
    // Round 2 (forward): softmax(dot(x, out0+out1)); write output
    route_passW<0, 1, 0><<<gW, blk>>>(x, bias, out);
}

// round 13
// speedup vs baseline: 1.0743x; 1.0743x over previous
#include <cuda_runtime.h>
#include <cuda_fp16.h>

// Problem constants
#define NB   32      // batch
#define NIN  2048    // input capsules
#define ROW  1024    // NOUT*DD floats per (b,i) row
// Pass 0 (column-per-thread, high occupancy):
#define SLICES0 32   // blocks per batch item (grid 1024, ~6 blocks/SM)
#define RPB0 (NIN / SLICES0)   // 64 rows per block
// Weighted passes (row-per-warp over fp16 shadow):
#define SLICES 8     // blocks per batch item (grid 256 = single resident wave)
#define WPBLK  8
#define IPW  32      // rows per warp

// Scratch (static device memory; no runtime allocation)
__device__ float  g_partials[NB * SLICES0 * ROW];   // 4 MB
__device__ float  g_ow[NB * ROW];                   // out0 / out0+out1
__device__ float2 g_xh[(size_t)NB * NIN * 256];     // fp16 shadow, 128 MB (row = 256 float2)
__device__ int    g_cnt[NB];                        // zero-init; self-resetting

// ---------------------------------------------------------------------------
// Last-block epilogue: reduce NSL partials in fixed order, + bias, squash,
// update g_ow / write output, reset counter (replay-safe).
// ---------------------------------------------------------------------------
template<int NSL, int OW_MODE, int FINAL_OUT>
__device__ __forceinline__ void last_block_epilogue(
    int b, const float* __restrict__ bias, float* __restrict__ dout)
{
    const int t = threadIdx.x;
    const float4* pp = reinterpret_cast<const float4*>(g_partials) + (size_t)b * NSL * 256;
    float4 r = make_float4(0.f, 0.f, 0.f, 0.f);
#pragma unroll 8
    for (int s2 = 0; s2 < NSL; s2++) {
        float4 v = __ldcg(pp + s2 * 256 + t);
        r.x += v.x; r.y += v.y; r.z += v.z; r.w += v.w;
    }
    float4 bb = reinterpret_cast<const float4*>(bias)[t];
    r.x += bb.x; r.y += bb.y; r.z += bb.z; r.w += bb.w;

    float n2 = r.x * r.x + r.y * r.y + r.z * r.z + r.w * r.w;
    n2 += __shfl_xor_sync(0xffffffffu, n2, 1);
    n2 += __shfl_xor_sync(0xffffffffu, n2, 2);
    float scale = n2 / ((1.0f + n2) * sqrtf(n2 + 1e-7f));
    float4 o = make_float4(r.x * scale, r.y * scale, r.z * scale, r.w * scale);

    if (FINAL_OUT)
        reinterpret_cast<float4*>(dout)[b * 256 + t] = o;
    if (OW_MODE == 1) {
        reinterpret_cast<float4*>(g_ow)[b * 256 + t] = o;
    } else if (OW_MODE == 2) {
        float4 c = reinterpret_cast<const float4*>(g_ow)[b * 256 + t];
        c.x += o.x; c.y += o.y; c.z += o.z; c.w += o.w;
        reinterpret_cast<float4*>(g_ow)[b * 256 + t] = c;
    }
    if (t == 0) g_cnt[b] = 0;
}

// Publish-then-arrive (all threads stored + fenced BEFORE t0 increments).
template<int NSL>
__device__ __forceinline__ bool arrive_last(int b)
{
    __threadfence();
    __syncthreads();
    __shared__ int isLast;
    if (threadIdx.x == 0) {
        int old = atomicAdd(&g_cnt[b], 1);
        isLast = (old == NSL - 1);
    }
    __syncthreads();
    return isLast != 0;
}

// ---------------------------------------------------------------------------
// Pass 0: column-per-thread, high occupancy (~48 warps/SM). Thread t owns
// fp32 float4-column t: reads 64 rows, converts to fp16 shadow (1 STG.64 per
// LDG.128), accumulates the uniform (1/64) sum. Low regs, no smem hot loop.
// ---------------------------------------------------------------------------
__global__ void __launch_bounds__(256, 6)
route_pass0(const float* __restrict__ x, const float* __restrict__ bias,
            float* __restrict__ dout)
{
    const int b     = blockIdx.x >> 5;
    const int slice = blockIdx.x & 31;
    const int t     = threadIdx.x;

    const float4* base = reinterpret_cast<const float4*>(x)
        + ((size_t)b * NIN + (size_t)slice * RPB0) * 256;
    float2* hbase = g_xh + ((size_t)b * NIN + (size_t)slice * RPB0) * 256;

    float4 acc = make_float4(0.f, 0.f, 0.f, 0.f);
    for (int ii = 0; ii < RPB0; ii += 8) {
        float4 v[8];
#pragma unroll
        for (int k = 0; k < 8; k++) v[k] = __ldcs(base + (size_t)(ii + k) * 256 + t);
#pragma unroll
        for (int k = 0; k < 8; k++) {
            __half2 h0 = __floats2half2_rn(v[k].x, v[k].y);
            __half2 h1 = __floats2half2_rn(v[k].z, v[k].w);
            float2 st;
            st.x = __uint_as_float(*reinterpret_cast<unsigned*>(&h0));
            st.y = __uint_as_float(*reinterpret_cast<unsigned*>(&h1));
            hbase[(size_t)(ii + k) * 256 + t] = st;   // evict-normal: L2-retained for pass 1
            acc.x += v[k].x; acc.y += v[k].y; acc.z += v[k].z; acc.w += v[k].w;
        }
    }
    acc.x *= 0.015625f; acc.y *= 0.015625f;   // 1/64 exact
    acc.z *= 0.015625f; acc.w *= 0.015625f;

    reinterpret_cast<float4*>(g_partials)[((size_t)b * SLICES0 + slice) * 256 + t] = acc;

    if (!arrive_last<SLICES0>(b)) return;
    last_block_epilogue<SLICES0, 1, 0>(b, bias, dout);
}

// ---------------------------------------------------------------------------
// Weighted passes over the fp16 shadow, row-per-warp, x2-row unroll, zigzag.
// fp16 mapping: float4 g = lane + 32k' (k'=0..3) -> halves [8g, 8g+8)
//   -> capsule j = (lane>>1) + 16k', d-range = (lane&1)*8 .. +8.
// Dot over d=16: xor 1 (lane pair). Softmax over 64 j: max/sum k' then
// xor 2,4,8,16. Weights in shared (wsh), accs 8 float4 per thread.
// ---------------------------------------------------------------------------
template<int OW_MODE, int FINAL_OUT, int REVERSE>
__global__ void __launch_bounds__(256, 2)
route_passH(const float* __restrict__ bias, float* __restrict__ dout)
{
    const int b     = blockIdx.x >> 3;
    const int slice = blockIdx.x & 7;
    const int wloc  = threadIdx.x >> 5;
    const int wb    = (slice << 3) | wloc;
    const int lane  = threadIdx.x & 31;

    __shared__ float4 wsh[256];            // 4 KB: ow vector for this b
    __shared__ float4 sbuf[WPBLK * 256];   // 32 KB: tail reduce

    {
        const float4* owp = reinterpret_cast<const float4*>(g_ow) + (size_t)b * 256;
        wsh[threadIdx.x] = owp[threadIdx.x];
    }
    __syncthreads();

    float4 acc[8];
#pragma unroll
    for (int k = 0; k < 8; k++) acc[k] = make_float4(0.f, 0.f, 0.f, 0.f);

    const float4* hbase = reinterpret_cast<const float4*>(g_xh)
        + ((size_t)b * NIN + (size_t)wb * IPW) * 128;   // 128 float4 per row

    for (int it = 0; it < IPW; it += 2) {
        const int ii0 = REVERSE ? (IPW - 1 - it) : it;
        const int ii1 = REVERSE ? (IPW - 2 - it) : (it + 1);
        const float4* r0 = hbase + (size_t)ii0 * 128;
        const float4* r1 = hbase + (size_t)ii1 * 128;

        float4 hv0[4], hv1[4];
#pragma unroll
        for (int k = 0; k < 4; k++) hv0[k] = r0[lane + 32 * k];
#pragma unroll
        for (int k = 0; k < 4; k++) hv1[k] = r1[lane + 32 * k];

        // unpack row 0 and row 1: 8 fp32 elements per float4 load
        float4 xv0[8], xv1[8];
#pragma unroll
        for (int k = 0; k < 4; k++) {
            const __half2* h0 = reinterpret_cast<const __half2*>(&hv0[k]);
            const __half2* h1 = reinterpret_cast<const __half2*>(&hv1[k]);
            float2 a0 = __half22float2(h0[0]), a1 = __half22float2(h0[1]);
            float2 a2 = __half22float2(h0[2]), a3 = __half22float2(h0[3]);
            xv0[2 * k]     = make_float4(a0.x, a0.y, a1.x, a1.y);
            xv0[2 * k + 1] = make_float4(a2.x, a2.y, a3.x, a3.y);
            float2 c0 = __half22float2(h1[0]), c1 = __half22float2(h1[1]);
            float2 c2 = __half22float2(h1[2]), c3 = __half22float2(h1[3]);
            xv1[2 * k]     = make_float4(c0.x, c0.y, c1.x, c1.y);
            xv1[2 * k + 1] = make_float4(c2.x, c2.y, c3.x, c3.y);
        }

        float p0[4], p1[4];
#pragma unroll
        for (int k = 0; k < 4; k++) {
            int g = lane + 32 * k;
            float4 wa = wsh[2 * g], wb2 = wsh[2 * g + 1];
            float t0 = xv0[2*k].x * wa.x + xv0[2*k].y * wa.y + xv0[2*k].z * wa.z + xv0[2*k].w * wa.w
                     + xv0[2*k+1].x * wb2.x + xv0[2*k+1].y * wb2.y + xv0[2*k+1].z * wb2.z + xv0[2*k+1].w * wb2.w;
            float t1 = xv1[2*k].x * wa.x + xv1[2*k].y * wa.y + xv1[2*k].z * wa.z + xv1[2*k].w * wa.w
                     + xv1[2*k+1].x * wb2.x + xv1[2*k+1].y * wb2.y + xv1[2*k+1].z * wb2.z + xv1[2*k+1].w * wb2.w;
            t0 += __shfl_xor_sync(0xffffffffu, t0, 1);   // full dot over d=16
            t1 += __shfl_xor_sync(0xffffffffu, t1, 1);
            p0[k] = t0; p1[k] = t1;
        }
        // softmax over all 64 j (two rows)
        float m0 = fmaxf(fmaxf(p0[0], p0[1]), fmaxf(p0[2], p0[3]));
        float m1 = fmaxf(fmaxf(p1[0], p1[1]), fmaxf(p1[2], p1[3]));
        m0 = fmaxf(m0, __shfl_xor_sync(0xffffffffu, m0, 2));
        m1 = fmaxf(m1, __shfl_xor_sync(0xffffffffu, m1, 2));
        m0 = fmaxf(m0, __shfl_xor_sync(0xffffffffu, m0, 4));
        m1 = fmaxf(m1, __shfl_xor_sync(0xffffffffu, m1, 4));
        m0 = fmaxf(m0, __shfl_xor_sync(0xffffffffu, m0, 8));
        m1 = fmaxf(m1, __shfl_xor_sync(0xffffffffu, m1, 8));
        m0 = fmaxf(m0, __shfl_xor_sync(0xffffffffu, m0, 16));
        m1 = fmaxf(m1, __shfl_xor_sync(0xffffffffu, m1, 16));
        float a0[4], a1[4], s0 = 0.f, s1 = 0.f;
#pragma unroll
        for (int k = 0; k < 4; k++) {
            a0[k] = __expf(p0[k] - m0); s0 += a0[k];
            a1[k] = __expf(p1[k] - m1); s1 += a1[k];
        }
        s0 += __shfl_xor_sync(0xffffffffu, s0, 2);
        s1 += __shfl_xor_sync(0xffffffffu, s1, 2);
        s0 += __shfl_xor_sync(0xffffffffu, s0, 4);
        s1 += __shfl_xor_sync(0xffffffffu, s1, 4);
        s0 += __shfl_xor_sync(0xffffffffu, s0, 8);
        s1 += __shfl_xor_sync(0xffffffffu, s1, 8);
        s0 += __shfl_xor_sync(0xffffffffu, s0, 16);
        s1 += __shfl_xor_sync(0xffffffffu, s1, 16);
        float inv0 = 1.0f / s0, inv1 = 1.0f / s1;
#pragma unroll
        for (int k = 0; k < 4; k++) {
            float ak0 = a0[k] * inv0;
            float ak1 = a1[k] * inv1;
#pragma unroll
            for (int h = 0; h < 2; h++) {
                int idx = 2 * k + h;
                acc[idx].x = fmaf(ak1, xv1[idx].x, fmaf(ak0, xv0[idx].x, acc[idx].x));
                acc[idx].y = fmaf(ak1, xv1[idx].y, fmaf(ak0, xv0[idx].y, acc[idx].y));
                acc[idx].z = fmaf(ak1, xv1[idx].z, fmaf(ak0, xv0[idx].z, acc[idx].z));
                acc[idx].w = fmaf(ak1, xv1[idx].w, fmaf(ak0, xv0[idx].w, acc[idx].w));
            }
        }
    }

    // in-block reduce: write accs to canonical float4 positions
#pragma unroll
    for (int k = 0; k < 4; k++) {
        int g = lane + 32 * k;
        sbuf[wloc * 256 + 2 * g]     = acc[2 * k];
        sbuf[wloc * 256 + 2 * g + 1] = acc[2 * k + 1];
    }
    __syncthreads();

    const int t = threadIdx.x;
    float4 s = make_float4(0.f, 0.f, 0.f, 0.f);
#pragma unroll
    for (int w2 = 0; w2 < WPBLK; w2++) {
        float4 v = sbuf[w2 * 256 + t];
        s.x += v.x; s.y += v.y; s.z += v.z; s.w += v.w;
    }
    reinterpret_cast<float4*>(g_partials)[((size_t)b * SLICES + slice) * 256 + t] = s;

    if (!arrive_last<SLICES>(b)) return;
    last_block_epilogue<SLICES, OW_MODE, FINAL_OUT>(b, bias, dout);
}

extern "C" void kernel_launch(void* const* d_in, const int* in_sizes, int n_in,
                              void* d_out, int out_size)
{
    const float* x    = (const float*)d_in[0];   // [32, 2048, 64, 16]
    const float* bias = (const float*)d_in[1];   // [64, 16]
    float* out = (float*)d_out;                  // [32, 64, 16]

    (void)in_sizes; (void)n_in; (void)out_size;

    dim3 g0(NB * SLICES0), gW(NB * SLICES), blk(256);

    // Round 0 (forward, column-mapped, 48 warps/SM): uniform 1/64 sum +
    // fp16 shadow emission; g_ow = out0 (computed from fp32 -> exact).
    route_pass0<<<g0, blk>>>(x, bias, out);
    // Round 1 (REVERSE over shadow): softmax(dot(x, out0)); g_ow = out0+out1
    route_passH<2, 0, 1><<<gW, blk>>>(bias, out);
    // Round 2 (forward over shadow): softmax(dot(x, out0+out1)); write output
    route_passH<0, 1, 0><<<gW, blk>>>(bias, out);
}